// round 1
// baseline (speedup 1.0000x reference)
#include <cuda_runtime.h>
#include <cuda_bf16.h>
#include <math_constants.h>

// ---------------------------------------------------------------------------
// Problem constants (from reference)
// ---------------------------------------------------------------------------
#define NN 50000
#define NE 800000
#define HID 64

// Encoded -inf under the order-preserving float->uint map (bits(-inf)=0xFF800000 -> ~bits)
#define ENC_NEG_INF 0x007FFFFFu

// ---------------------------------------------------------------------------
// Scratch (device globals: allocation-free per harness rules)
// ---------------------------------------------------------------------------
__device__ __align__(16) float    g_n    [NN * HID];  // relu(x@Wn+bn)
__device__ __align__(16) float    g_m0   [NN * HID];  // n @ W1_rel[0]
__device__ __align__(16) float    g_m1   [NN * HID];  // n @ W1_rel[1]
__device__ __align__(16) float    g_agg1 [NN * HID];  // n@W1_root+b1, then += messages
__device__ __align__(16) float    g_h    [NN * HID];  // relu(agg1)
__device__ __align__(16) unsigned g_p0   [NN * HID];  // enc(h @ W2_rel[0])
__device__ __align__(16) unsigned g_p1   [NN * HID];  // enc(h @ W2_rel[1])
__device__ __align__(16) float    g_hr2  [NN * HID];  // h@W2_root+b2
__device__ __align__(16) unsigned g_agg2 [NN * HID];  // encoded running max

// ---------------------------------------------------------------------------
// Order-preserving float <-> uint map (total order; max(enc) == enc(max))
// ---------------------------------------------------------------------------
__device__ __forceinline__ unsigned enc_ord(float f) {
    unsigned b = __float_as_uint(f);
    return (b & 0x80000000u) ? ~b : (b | 0x80000000u);
}
__device__ __forceinline__ float dec_ord(unsigned u) {
    unsigned b = (u & 0x80000000u) ? (u ^ 0x80000000u) : ~u;
    return __uint_as_float(b);
}

// ---------------------------------------------------------------------------
// Kernel A: n = relu(x @ Wn + bn)       [NN,3]x[3,64]
// one thread per (node, col)
// ---------------------------------------------------------------------------
__global__ void k_node_embed(const float* __restrict__ x,
                             const float* __restrict__ Wn,
                             const float* __restrict__ bn) {
    int i = blockIdx.x * blockDim.x + threadIdx.x;
    if (i >= NN * HID) return;
    int node = i >> 6;
    int c    = i & 63;
    float x0 = __ldg(&x[node * 3 + 0]);
    float x1 = __ldg(&x[node * 3 + 1]);
    float x2 = __ldg(&x[node * 3 + 2]);
    float v = fmaf(x0, __ldg(&Wn[c]),
              fmaf(x1, __ldg(&Wn[64 + c]),
              fmaf(x2, __ldg(&Wn[128 + c]), __ldg(&bn[c]))));
    g_n[i] = fmaxf(v, 0.f);
}

// ---------------------------------------------------------------------------
// Generic node GEMM: out[N,64] = in[N,64] @ W[64,64] (+bias) (opt. ordered-uint encode)
// Block: 256 threads, 64 nodes; smem tiles; 4x4 register blocking.
// ---------------------------------------------------------------------------
#define NPB 64
__global__ void k_node_gemm(const float* __restrict__ in,
                            const float* __restrict__ W,
                            const float* __restrict__ bias,
                            void* __restrict__ out,
                            int encode) {
    __shared__ float sW[64 * 64];
    __shared__ float sIn[NPB * 65];   // +1 pad avoids bank conflicts
    int tid = threadIdx.x;
    int nbase = blockIdx.x * NPB;

    #pragma unroll
    for (int i = tid * 4; i < 64 * 64; i += 256 * 4)
        *(float4*)&sW[i] = *(const float4*)&W[i];

    for (int i = tid; i < NPB * 64; i += 256) {
        int nd = i >> 6, k = i & 63;
        int node = nbase + nd;
        sIn[nd * 65 + k] = (node < NN) ? in[node * 64 + k] : 0.f;
    }
    __syncthreads();

    int tx = tid & 15, ty = tid >> 4;
    int c0 = tx * 4, n0 = ty * 4;
    float acc[4][4] = {};

    #pragma unroll 4
    for (int k = 0; k < 64; k++) {
        float4 w = *(float4*)&sW[k * 64 + c0];
        #pragma unroll
        for (int j = 0; j < 4; j++) {
            float a = sIn[(n0 + j) * 65 + k];
            acc[j][0] = fmaf(a, w.x, acc[j][0]);
            acc[j][1] = fmaf(a, w.y, acc[j][1]);
            acc[j][2] = fmaf(a, w.z, acc[j][2]);
            acc[j][3] = fmaf(a, w.w, acc[j][3]);
        }
    }

    float b0 = 0.f, b1v = 0.f, b2v = 0.f, b3 = 0.f;
    if (bias) { b0 = bias[c0]; b1v = bias[c0 + 1]; b2v = bias[c0 + 2]; b3 = bias[c0 + 3]; }

    #pragma unroll
    for (int j = 0; j < 4; j++) {
        int node = nbase + n0 + j;
        if (node >= NN) break;
        float v0 = acc[j][0] + b0, v1 = acc[j][1] + b1v;
        float v2 = acc[j][2] + b2v, v3 = acc[j][3] + b3;
        if (encode) {
            uint4 u = make_uint4(enc_ord(v0), enc_ord(v1), enc_ord(v2), enc_ord(v3));
            *(uint4*)((unsigned*)out + node * 64 + c0) = u;
        } else {
            *(float4*)((float*)out + node * 64 + c0) = make_float4(v0, v1, v2, v3);
        }
    }
}

// ---------------------------------------------------------------------------
// conv1 edge pass: msg = m_{etype}[src] + relu(edge_attr@We+be) @ W1_edge
//                  agg1[dst] += msg   (red.add.f32)
// warp handles 4 edges/iter; lane t owns output cols (2t, 2t+1)
// ---------------------------------------------------------------------------
__global__ void k_edge1(const int*   __restrict__ ei,
                        const float* __restrict__ ea,
                        const int*   __restrict__ et,
                        const float* __restrict__ We,
                        const float* __restrict__ be,
                        const float* __restrict__ W1e) {
    __shared__ float  sWe[64];
    __shared__ float  sbe[32];
    __shared__ float2 sW1e[32 * 32];    // [k][colpair]
    int tid = threadIdx.x;
    if (tid < 64) sWe[tid] = We[tid];
    if (tid < 32) sbe[tid] = be[tid];
    for (int i = tid; i < 32 * 32; i += blockDim.x)
        sW1e[i] = ((const float2*)W1e)[i];
    __syncthreads();

    int lane   = tid & 31;
    int wid    = (blockIdx.x * blockDim.x + tid) >> 5;
    int nwarps = (gridDim.x * blockDim.x) >> 5;

    for (int base = wid * 4; base < NE; base += nwarps * 4) {
        float  ev[4];
        float2 acc[4];
        int    dstj[4];
        bool   valid[4];
        #pragma unroll
        for (int j = 0; j < 4; j++) {
            int e = base + j;
            valid[j] = (e < NE);
            if (!valid[j]) { ev[j] = 0.f; acc[j] = make_float2(0.f, 0.f); dstj[j] = 0; continue; }
            int src  = __ldg(&ei[e]);
            dstj[j]  = __ldg(&ei[NE + e]);
            int typ  = __ldg(&et[e]);
            float a0 = __ldg(&ea[2 * e]);
            float a1 = __ldg(&ea[2 * e + 1]);
            ev[j] = fmaxf(fmaf(a0, sWe[lane], fmaf(a1, sWe[32 + lane], sbe[lane])), 0.f);
            const float2* msel = (const float2*)(typ == 0 ? g_m0 : g_m1);
            acc[j] = __ldg(&msel[src * 32 + lane]);
        }
        #pragma unroll
        for (int k = 0; k < 32; k++) {
            float2 w = sW1e[k * 32 + lane];
            #pragma unroll
            for (int j = 0; j < 4; j++) {
                float ek = __shfl_sync(0xffffffffu, ev[j], k);
                acc[j].x = fmaf(ek, w.x, acc[j].x);
                acc[j].y = fmaf(ek, w.y, acc[j].y);
            }
        }
        #pragma unroll
        for (int j = 0; j < 4; j++) {
            if (!valid[j]) continue;
            float* p = &g_agg1[dstj[j] * 64 + lane * 2];
            atomicAdd(p,     acc[j].x);
            atomicAdd(p + 1, acc[j].y);
        }
    }
}

// ---------------------------------------------------------------------------
// h = relu(agg1); agg2 = enc(-inf)
// ---------------------------------------------------------------------------
__global__ void k_relu_init() {
    int i = blockIdx.x * blockDim.x + threadIdx.x;
    if (i >= NN * HID) return;
    g_h[i]    = fmaxf(g_agg1[i], 0.f);
    g_agg2[i] = ENC_NEG_INF;
}

// ---------------------------------------------------------------------------
// conv2 edge pass: agg2[dst] = max(agg2[dst], p_{etype}[src])  (red.max.u32)
// ---------------------------------------------------------------------------
__global__ void k_edge2(const int* __restrict__ ei,
                        const int* __restrict__ et) {
    int tid    = threadIdx.x;
    int lane   = tid & 31;
    int wid    = (blockIdx.x * blockDim.x + tid) >> 5;
    int nwarps = (gridDim.x * blockDim.x) >> 5;

    for (int base = wid * 4; base < NE; base += nwarps * 4) {
        #pragma unroll
        for (int j = 0; j < 4; j++) {
            int e = base + j;
            if (e >= NE) break;
            int src = __ldg(&ei[e]);
            int dst = __ldg(&ei[NE + e]);
            int typ = __ldg(&et[e]);
            const uint2* psel = (const uint2*)(typ == 0 ? g_p0 : g_p1);
            uint2 v = __ldg(&psel[src * 32 + lane]);
            unsigned* p = &g_agg2[dst * 64 + lane * 2];
            atomicMax(p,     v.x);
            atomicMax(p + 1, v.y);
        }
    }
}

// ---------------------------------------------------------------------------
// final: h2 = relu(where(finite,dec(agg2),0) + hroot2); out = tanh(h2@Wc+bc)*5
// one warp per node; lane t owns cols (2t, 2t+1)
// ---------------------------------------------------------------------------
__global__ void k_final(const float* __restrict__ Wc,
                        const float* __restrict__ bc,
                        float* __restrict__ out) {
    __shared__ float sWc[64];
    int tid = threadIdx.x;
    if (tid < 64) sWc[tid] = Wc[tid];
    __syncthreads();

    int node = ((blockIdx.x * blockDim.x + tid) >> 5);
    int lane = tid & 31;
    if (node >= NN) return;

    uint2  a = *(const uint2*)&g_agg2[node * 64 + 2 * lane];
    float2 r = *(const float2*)&g_hr2[node * 64 + 2 * lane];
    float f0 = dec_ord(a.x);
    float f1 = dec_ord(a.y);
    if (!isfinite(f0)) f0 = 0.f;
    if (!isfinite(f1)) f1 = 0.f;
    float h0 = fmaxf(f0 + r.x, 0.f);
    float h1 = fmaxf(f1 + r.y, 0.f);
    float p = fmaf(h0, sWc[2 * lane], h1 * sWc[2 * lane + 1]);
    #pragma unroll
    for (int o = 16; o > 0; o >>= 1) p += __shfl_xor_sync(0xffffffffu, p, o);
    if (lane == 0) out[node] = tanhf(p + __ldg(bc)) * 5.0f;
}

// ---------------------------------------------------------------------------
// launch
// ---------------------------------------------------------------------------
extern "C" void kernel_launch(void* const* d_in, const int* in_sizes, int n_in,
                              void* d_out, int out_size) {
    const float* x      = (const float*)d_in[0];
    const int*   ei     = (const int*)  d_in[1];
    const float* ea     = (const float*)d_in[2];
    const int*   et     = (const int*)  d_in[3];
    const float* Wn     = (const float*)d_in[4];
    const float* bn     = (const float*)d_in[5];
    const float* We     = (const float*)d_in[6];
    const float* be     = (const float*)d_in[7];
    const float* W1_rel = (const float*)d_in[8];
    const float* W1_edge= (const float*)d_in[9];
    const float* W1_root= (const float*)d_in[10];
    const float* b1     = (const float*)d_in[11];
    const float* W2_rel = (const float*)d_in[12];
    const float* W2_root= (const float*)d_in[13];
    const float* b2     = (const float*)d_in[14];
    const float* Wc     = (const float*)d_in[15];
    const float* bc     = (const float*)d_in[16];
    float* out          = (float*)d_out;

    float *pm0, *pm1, *pagg1, *phr2;
    unsigned *pp0, *pp1;
    cudaGetSymbolAddress((void**)&pm0,  g_m0);
    cudaGetSymbolAddress((void**)&pm1,  g_m1);
    cudaGetSymbolAddress((void**)&pagg1,g_agg1);
    cudaGetSymbolAddress((void**)&phr2, g_hr2);
    cudaGetSymbolAddress((void**)&pp0,  g_p0);
    cudaGetSymbolAddress((void**)&pp1,  g_p1);
    float* pn; cudaGetSymbolAddress((void**)&pn, g_n);
    float* ph; cudaGetSymbolAddress((void**)&ph, g_h);

    const int elemBlocks = (NN * HID + 255) / 256;
    const int gemmBlocks = (NN + NPB - 1) / NPB;

    // node embedding
    k_node_embed<<<elemBlocks, 256>>>(x, Wn, bn);

    // conv1 node-side precompute
    k_node_gemm<<<gemmBlocks, 256>>>(pn, W1_rel,        nullptr, pm0,   0);
    k_node_gemm<<<gemmBlocks, 256>>>(pn, W1_rel + 4096, nullptr, pm1,   0);
    k_node_gemm<<<gemmBlocks, 256>>>(pn, W1_root,       b1,      pagg1, 0);

    // conv1 edge scatter (sum)
    k_edge1<<<2048, 256>>>(ei, ea, et, We, be, W1_edge);

    // relu + agg2 init
    k_relu_init<<<elemBlocks, 256>>>();

    // conv2 node-side precompute (rel outputs encoded for uint max)
    k_node_gemm<<<gemmBlocks, 256>>>(ph, W2_rel,        nullptr, pp0,  1);
    k_node_gemm<<<gemmBlocks, 256>>>(ph, W2_rel + 4096, nullptr, pp1,  1);
    k_node_gemm<<<gemmBlocks, 256>>>(ph, W2_root,       b2,      phr2, 0);

    // conv2 edge scatter (max)
    k_edge2<<<2048, 256>>>(ei, et);

    // readout
    k_final<<<(NN * 32 + 255) / 256, 256>>>(Wc, bc, out);
}

// round 2
// speedup vs baseline: 1.8574x; 1.8574x over previous
#include <cuda_runtime.h>
#include <cuda_bf16.h>
#include <math_constants.h>

#define NN 50000
#define NE 800000
#define HID 64
#define FULL 0xffffffffu

// ---------------------------------------------------------------------------
// Scratch (device globals; allocation-free per harness rules)
// ---------------------------------------------------------------------------
__device__ __align__(16) float    g_m0  [NN * HID];   // n @ W1_rel[0]
__device__ __align__(16) float    g_m1  [NN * HID];   // n @ W1_rel[1]
__device__ __align__(16) float    g_r1  [NN * HID];   // n @ W1_root + b1
__device__ __align__(16) float    g_hpre[NN * HID];   // pre-relu h (conv1 out)
__device__ __align__(16) float    g_p0  [NN * HID];   // h @ W2_rel[0]
__device__ __align__(16) float    g_p1  [NN * HID];   // h @ W2_rel[1]
__device__ __align__(16) float    g_r2  [NN * HID];   // h @ W2_root + b2
// CSR by dst
__device__ int      g_deg[NN];
__device__ int      g_off[NN + 1];
__device__ int      g_cur[NN];
__device__ unsigned g_csr_pk[NE];                     // src | (typ<<31)
__device__ __align__(8) float2 g_csr_ea[NE];          // edge_attr gathered to CSR order

// ---------------------------------------------------------------------------
// CSR build: histogram, block-wide scan (1 block), fill
// ---------------------------------------------------------------------------
__global__ void k_hist(const int* __restrict__ ei) {
    int e = blockIdx.x * blockDim.x + threadIdx.x;
    if (e < NE) atomicAdd(&g_deg[ei[NE + e]], 1);
}

__global__ void k_scan() {
    __shared__ int warpsum[32];
    int tid  = threadIdx.x;
    int lane = tid & 31;
    int wid  = tid >> 5;
    int carry = 0;
    for (int base = 0; base < NN; base += 1024) {
        int i = base + tid;
        int v = (i < NN) ? g_deg[i] : 0;
        int s = v;
        #pragma unroll
        for (int o = 1; o < 32; o <<= 1) {
            int t = __shfl_up_sync(FULL, s, o);
            if (lane >= o) s += t;
        }
        if (lane == 31) warpsum[wid] = s;
        __syncthreads();
        if (wid == 0) {
            int ws = warpsum[lane];
            #pragma unroll
            for (int o = 1; o < 32; o <<= 1) {
                int t = __shfl_up_sync(FULL, ws, o);
                if (lane >= o) ws += t;
            }
            warpsum[lane] = ws;
        }
        __syncthreads();
        int wpre = (wid > 0) ? warpsum[wid - 1] : 0;
        int excl = carry + wpre + s - v;
        if (i < NN) { g_off[i] = excl; g_cur[i] = excl; }
        int total = warpsum[31];
        __syncthreads();
        carry += total;
    }
    if (tid == 0) g_off[NN] = NE;
}

__global__ void k_fill(const int* __restrict__ ei,
                       const float* __restrict__ ea,
                       const int* __restrict__ et) {
    int e = blockIdx.x * blockDim.x + threadIdx.x;
    if (e >= NE) return;
    int dst = ei[NE + e];
    int pos = atomicAdd(&g_cur[dst], 1);
    g_csr_pk[pos] = (unsigned)ei[e] | ((unsigned)et[e] << 31);
    g_csr_ea[pos] = ((const float2*)ea)[e];
}

// ---------------------------------------------------------------------------
// Fused triple GEMM: out{0,1,2}[N,64] = f(in)[N,64] @ {W0,W1,W2}  (+bias on W2)
// mode 0: f(in) = relu(x@Wn+bn) (embed fused);  mode 1: f(in) = relu(in)
// 256 threads, 64 nodes/block; each thread: 4 cols x 4 nodes x 3 matrices.
// ---------------------------------------------------------------------------
#define NPB 64
#define INPAD 68
extern __shared__ float s_dyn[];
__global__ void k_gemm3(const float* __restrict__ in,
                        const float* __restrict__ W0,
                        const float* __restrict__ W1,
                        const float* __restrict__ W2,
                        const float* __restrict__ bias2,
                        const float* __restrict__ Wn,
                        const float* __restrict__ bn,
                        float* __restrict__ o0,
                        float* __restrict__ o1,
                        float* __restrict__ o2,
                        int mode) {
    float* sW  = s_dyn;                 // 3 * 64 * 64
    float* sIn = s_dyn + 3 * 4096;      // 64 * INPAD
    __shared__ float sX[NPB * 3];
    int tid = threadIdx.x;
    int nbase = blockIdx.x * NPB;

    for (int i = tid * 4; i < 4096; i += 1024) {
        *(float4*)&sW[i]        = *(const float4*)&W0[i];
        *(float4*)&sW[4096 + i] = *(const float4*)&W1[i];
        *(float4*)&sW[8192 + i] = *(const float4*)&W2[i];
    }

    if (mode == 0) {
        if (tid < NPB * 3) {
            int nd = tid / 3, c = tid % 3;
            int node = nbase + nd;
            sX[tid] = (node < NN) ? __ldg(&in[node * 3 + c]) : 0.f;
        }
        __syncthreads();
        for (int i = tid; i < NPB * 64; i += 256) {
            int nd = i >> 6, k = i & 63;
            float v = fmaf(sX[nd * 3 + 0], __ldg(&Wn[k]),
                      fmaf(sX[nd * 3 + 1], __ldg(&Wn[64 + k]),
                      fmaf(sX[nd * 3 + 2], __ldg(&Wn[128 + k]), __ldg(&bn[k]))));
            sIn[nd * INPAD + k] = fmaxf(v, 0.f);
        }
    } else {
        for (int i = tid * 4; i < NPB * 64; i += 1024) {
            int nd = i >> 6, k = i & 63;
            int node = nbase + nd;
            float4 v = make_float4(0.f, 0.f, 0.f, 0.f);
            if (node < NN) v = *(const float4*)&in[node * 64 + k];
            v.x = fmaxf(v.x, 0.f); v.y = fmaxf(v.y, 0.f);
            v.z = fmaxf(v.z, 0.f); v.w = fmaxf(v.w, 0.f);
            *(float4*)&sIn[nd * INPAD + k] = v;
        }
    }
    __syncthreads();

    int tx = tid & 15, ty = tid >> 4;
    int c0 = tx * 4, n0 = ty * 4;
    float acc[3][4][4] = {};

    #pragma unroll 2
    for (int k = 0; k < 64; k++) {
        float4 w0 = *(float4*)&sW[k * 64 + c0];
        float4 w1 = *(float4*)&sW[4096 + k * 64 + c0];
        float4 w2 = *(float4*)&sW[8192 + k * 64 + c0];
        float a[4];
        #pragma unroll
        for (int j = 0; j < 4; j++) a[j] = sIn[(n0 + j) * INPAD + k];
        #pragma unroll
        for (int j = 0; j < 4; j++) {
            acc[0][j][0] = fmaf(a[j], w0.x, acc[0][j][0]);
            acc[0][j][1] = fmaf(a[j], w0.y, acc[0][j][1]);
            acc[0][j][2] = fmaf(a[j], w0.z, acc[0][j][2]);
            acc[0][j][3] = fmaf(a[j], w0.w, acc[0][j][3]);
            acc[1][j][0] = fmaf(a[j], w1.x, acc[1][j][0]);
            acc[1][j][1] = fmaf(a[j], w1.y, acc[1][j][1]);
            acc[1][j][2] = fmaf(a[j], w1.z, acc[1][j][2]);
            acc[1][j][3] = fmaf(a[j], w1.w, acc[1][j][3]);
            acc[2][j][0] = fmaf(a[j], w2.x, acc[2][j][0]);
            acc[2][j][1] = fmaf(a[j], w2.y, acc[2][j][1]);
            acc[2][j][2] = fmaf(a[j], w2.z, acc[2][j][2]);
            acc[2][j][3] = fmaf(a[j], w2.w, acc[2][j][3]);
        }
    }

    float4 b2 = *(const float4*)&bias2[c0];
    #pragma unroll
    for (int j = 0; j < 4; j++) {
        int node = nbase + n0 + j;
        if (node >= NN) break;
        *(float4*)&o0[node * 64 + c0] =
            make_float4(acc[0][j][0], acc[0][j][1], acc[0][j][2], acc[0][j][3]);
        *(float4*)&o1[node * 64 + c0] =
            make_float4(acc[1][j][0], acc[1][j][1], acc[1][j][2], acc[1][j][3]);
        *(float4*)&o2[node * 64 + c0] =
            make_float4(acc[2][j][0] + b2.x, acc[2][j][1] + b2.y,
                        acc[2][j][2] + b2.z, acc[2][j][3] + b2.w);
    }
}

// ---------------------------------------------------------------------------
// conv1 gather: one warp per dst node.
//   msum  = sum_e m_{typ}[src]          (lane owns cols 2l, 2l+1)
//   aggev = sum_e relu(ea@We+be)        (lane owns dim l of 32)
//   hpre  = r1 + msum + aggev @ W1_edge
// ---------------------------------------------------------------------------
__global__ void k_gather1(const float* __restrict__ We,
                          const float* __restrict__ be,
                          const float* __restrict__ W1e) {
    __shared__ float  sWe0[32], sWe1[32], sbe[32];
    __shared__ float2 sW1e[32 * 32];
    int tid = threadIdx.x;
    if (tid < 32) { sWe0[tid] = We[tid]; sWe1[tid] = We[32 + tid]; sbe[tid] = be[tid]; }
    for (int i = tid; i < 1024; i += blockDim.x)
        sW1e[i] = ((const float2*)W1e)[i];
    __syncthreads();

    int lane = tid & 31;
    int node = (blockIdx.x * blockDim.x + tid) >> 5;
    if (node >= NN) return;
    int s0 = g_off[node], s1 = g_off[node + 1];

    float  ev = 0.f;
    float2 ms = make_float2(0.f, 0.f);
    for (int e = s0; e < s1; e++) {
        unsigned pk = __ldg(&g_csr_pk[e]);
        float2 a = __ldg(&g_csr_ea[e]);
        ev += fmaxf(fmaf(a.x, sWe0[lane], fmaf(a.y, sWe1[lane], sbe[lane])), 0.f);
        const float2* m = (pk >> 31) ? (const float2*)g_m1 : (const float2*)g_m0;
        float2 v = __ldg(&m[(pk & 0x7FFFFFFFu) * 32 + lane]);
        ms.x += v.x; ms.y += v.y;
    }

    float2 acc = make_float2(0.f, 0.f);
    #pragma unroll
    for (int k = 0; k < 32; k++) {
        float ek = __shfl_sync(FULL, ev, k);
        float2 w = sW1e[k * 32 + lane];
        acc.x = fmaf(ek, w.x, acc.x);
        acc.y = fmaf(ek, w.y, acc.y);
    }
    float2 r = *(const float2*)&g_r1[node * 64 + 2 * lane];
    *(float2*)&g_hpre[node * 64 + 2 * lane] =
        make_float2(r.x + ms.x + acc.x, r.y + ms.y + acc.y);
}

// ---------------------------------------------------------------------------
// conv2 gather + readout: one warp per dst node.
//   mx  = max_e p_{typ}[src]   (0 for empty segment)
//   h2  = relu(mx + r2);  out = tanh(h2 @ Wc + bc) * 5
// ---------------------------------------------------------------------------
__global__ void k_gather2(const float* __restrict__ Wc,
                          const float* __restrict__ bc,
                          float* __restrict__ out) {
    int tid  = threadIdx.x;
    int lane = tid & 31;
    int node = (blockIdx.x * blockDim.x + tid) >> 5;
    if (node >= NN) return;
    int s0 = g_off[node], s1 = g_off[node + 1];

    float2 mx = make_float2(-CUDART_INF_F, -CUDART_INF_F);
    for (int e = s0; e < s1; e++) {
        unsigned pk = __ldg(&g_csr_pk[e]);
        const float2* p = (pk >> 31) ? (const float2*)g_p1 : (const float2*)g_p0;
        float2 v = __ldg(&p[(pk & 0x7FFFFFFFu) * 32 + lane]);
        mx.x = fmaxf(mx.x, v.x);
        mx.y = fmaxf(mx.y, v.y);
    }
    if (s1 == s0) mx = make_float2(0.f, 0.f);

    float2 r = *(const float2*)&g_r2[node * 64 + 2 * lane];
    float h0 = fmaxf(mx.x + r.x, 0.f);
    float h1 = fmaxf(mx.y + r.y, 0.f);
    float p = fmaf(h0, __ldg(&Wc[2 * lane]), h1 * __ldg(&Wc[2 * lane + 1]));
    #pragma unroll
    for (int o = 16; o > 0; o >>= 1) p += __shfl_xor_sync(FULL, p, o);
    if (lane == 0) out[node] = tanhf(p + __ldg(bc)) * 5.0f;
}

// ---------------------------------------------------------------------------
// launch
// ---------------------------------------------------------------------------
extern "C" void kernel_launch(void* const* d_in, const int* in_sizes, int n_in,
                              void* d_out, int out_size) {
    const float* x      = (const float*)d_in[0];
    const int*   ei     = (const int*)  d_in[1];
    const float* ea     = (const float*)d_in[2];
    const int*   et     = (const int*)  d_in[3];
    const float* Wn     = (const float*)d_in[4];
    const float* bn     = (const float*)d_in[5];
    const float* We     = (const float*)d_in[6];
    const float* be     = (const float*)d_in[7];
    const float* W1_rel = (const float*)d_in[8];
    const float* W1_edge= (const float*)d_in[9];
    const float* W1_root= (const float*)d_in[10];
    const float* b1     = (const float*)d_in[11];
    const float* W2_rel = (const float*)d_in[12];
    const float* W2_root= (const float*)d_in[13];
    const float* b2     = (const float*)d_in[14];
    const float* Wc     = (const float*)d_in[15];
    const float* bc     = (const float*)d_in[16];
    float* out          = (float*)d_out;

    float *pm0, *pm1, *pr1, *phpre, *pp0, *pp1, *pr2;
    int* pdeg;
    cudaGetSymbolAddress((void**)&pm0,   g_m0);
    cudaGetSymbolAddress((void**)&pm1,   g_m1);
    cudaGetSymbolAddress((void**)&pr1,   g_r1);
    cudaGetSymbolAddress((void**)&phpre, g_hpre);
    cudaGetSymbolAddress((void**)&pp0,   g_p0);
    cudaGetSymbolAddress((void**)&pp1,   g_p1);
    cudaGetSymbolAddress((void**)&pr2,   g_r2);
    cudaGetSymbolAddress((void**)&pdeg,  g_deg);

    static const int SMEM = (3 * 4096 + NPB * INPAD) * sizeof(float);
    cudaFuncSetAttribute(k_gemm3, cudaFuncAttributeMaxDynamicSharedMemorySize, SMEM);

    const int gemmBlocks = (NN + NPB - 1) / NPB;
    const int edgeBlocks = (NE + 255) / 256;
    const int nodeWarpBlocks = (NN * 32 + 255) / 256;

    // CSR build (shared by both convs)
    cudaMemsetAsync(pdeg, 0, NN * sizeof(int));
    k_hist<<<edgeBlocks, 256>>>(ei);
    k_scan<<<1, 1024>>>();
    k_fill<<<edgeBlocks, 256>>>(ei, ea, et);

    // conv1 node-side: n = relu(x@Wn+bn) fused; m0, m1, r1
    k_gemm3<<<gemmBlocks, 256, SMEM>>>(x, W1_rel, W1_rel + 4096, W1_root, b1,
                                       Wn, bn, pm0, pm1, pr1, 0);
    // conv1 gather (sum) + edge-feature fold
    k_gather1<<<nodeWarpBlocks, 256>>>(We, be, W1_edge);

    // conv2 node-side: h = relu(hpre) fused; p0, p1, r2
    k_gemm3<<<gemmBlocks, 256, SMEM>>>(phpre, W2_rel, W2_rel + 4096, W2_root, b2,
                                       nullptr, nullptr, pp0, pp1, pr2, 1);
    // conv2 gather (max) + readout fused
    k_gather2<<<nodeWarpBlocks, 256>>>(Wc, bc, out);
}